// round 13
// baseline (speedup 1.0000x reference)
#include <cuda_runtime.h>

// CRZ (DIM=2, WIRES=12, control=0, target=1, J=1): diagonal unitary, phase
// depends only on the top two bits of row n (n in [0,4096)), BATCH=2048.
//   region 0,1 (n < 2048)        : d = 1
//   region 2   (2048 <= n < 3072): d = exp(-i*a),  a = 0.5 * angle
//   region 3   (3072 <= n < 4096): d = exp(+i*a)
// Harness output is FLOAT32 [D*BATCH] = real part: out = re*pc - im*ps.
//
// R10 resubmit (R11 was an infra failure, kernel never ran):
// 256-bit (.v4.b64) accesses carry L2 evict hints on sm_103a. Inputs:
// evict_last (pin 64MB in L2 across graph replays). Output: evict_first
// (write-once stream). 4 x 32B chunks per thread per plane, block-strided,
// fully coalesced.

#define D_DIM   4096
#define BATCH   2048
#define TOTAL   (D_DIM * BATCH)        // 8388608 float32 elements
#define THREADS 256
#define PER_V   4                      // 32B chunks per thread
#define FLOATS_PER_CHUNK 8
#define CHUNKS_TOTAL (TOTAL / FLOATS_PER_CHUNK)        // 1048576
#define CHUNKS_PER_BLOCK (THREADS * PER_V)             // 1024 chunks = 8192 elems

struct U64x4 { unsigned long long a, b, c, d; };

__device__ __forceinline__ U64x4 ld256_evict_last(const void* p) {
    U64x4 v;
    asm volatile("ld.global.L2::evict_last.v4.b64 {%0,%1,%2,%3}, [%4];"
                 : "=l"(v.a), "=l"(v.b), "=l"(v.c), "=l"(v.d)
                 : "l"(p));
    return v;
}

__device__ __forceinline__ void st256_evict_first(void* p, U64x4 v) {
    asm volatile("st.global.L2::evict_first.v4.b64 [%0], {%1,%2,%3,%4};"
                 :: "l"(p), "l"(v.a), "l"(v.b), "l"(v.c), "l"(v.d)
                 : "memory");
}

__device__ __forceinline__ float2 unpack(unsigned long long u) {
    float2 f;
    asm("mov.b64 {%0,%1}, %2;" : "=f"(f.x), "=f"(f.y) : "l"(u));
    return f;
}

__device__ __forceinline__ unsigned long long pack(float x, float y) {
    unsigned long long u;
    asm("mov.b64 %0, {%1,%2};" : "=l"(u) : "f"(x), "f"(y));
    return u;
}

__device__ __forceinline__ unsigned long long cplx_real2(
    unsigned long long re_u, unsigned long long im_u, float pc, float ps) {
    float2 re = unpack(re_u);
    float2 im = unpack(im_u);
    return pack(fmaf(re.x, pc, -im.x * ps), fmaf(re.y, pc, -im.y * ps));
}

__global__ __launch_bounds__(THREADS) void crz_kernel(
    const char* __restrict__ xre,
    const char* __restrict__ xim,
    const float* __restrict__ angle,
    char* __restrict__ out)
{
    // chunk index (32B units), block-strided
    int base = blockIdx.x * CHUNKS_PER_BLOCK + threadIdx.x;

    // Block covers elements [blockIdx*8192, +8192); region = elem >> 21
    // -> region = blockIdx >> 8 (uniform per block; 1024 blocks total).
    int region = blockIdx.x >> 8;      // 0..3

    float a = (angle != nullptr) ? 0.5f * angle[0] : 0.0f;
    float s, c;
    __sincosf(a, &s, &c);

    float pc = (region >= 2) ? c : 1.0f;
    float ps = (region == 2) ? -s : ((region == 3) ? s : 0.0f);

    // Front-batched 8 x 256-bit loads (fully coalesced: warp = 1KB runs).
    U64x4 re[PER_V], im[PER_V];
#pragma unroll
    for (int k = 0; k < PER_V; k++)
        re[k] = ld256_evict_last(xre + (size_t)(base + k * THREADS) * 32);
#pragma unroll
    for (int k = 0; k < PER_V; k++)
        im[k] = ld256_evict_last(xim + (size_t)(base + k * THREADS) * 32);

#pragma unroll
    for (int k = 0; k < PER_V; k++) {
        U64x4 o;
        o.a = cplx_real2(re[k].a, im[k].a, pc, ps);
        o.b = cplx_real2(re[k].b, im[k].b, pc, ps);
        o.c = cplx_real2(re[k].c, im[k].c, pc, ps);
        o.d = cplx_real2(re[k].d, im[k].d, pc, ps);
        st256_evict_first(out + (size_t)(base + k * THREADS) * 32, o);
    }
}

extern "C" void kernel_launch(void* const* d_in, const int* in_sizes, int n_in,
                              void* d_out, int out_size)
{
    // Size-based mapping: size-1 tensor is angle; the two TOTAL-sized tensors
    // are (x_real, x_imag) in original relative order. Positional fallback.
    const float* angle = nullptr;
    const void* planes[2] = {nullptr, nullptr};
    int np = 0;
    for (int i = 0; i < n_in; i++) {
        if (in_sizes[i] == 1) {
            if (angle == nullptr) angle = (const float*)d_in[i];
        } else if (in_sizes[i] == TOTAL && np < 2) {
            planes[np++] = d_in[i];
        }
    }
    if (np < 2) {
        np = 0;
        for (int i = 0; i < n_in && np < 2; i++)
            if (in_sizes[i] > 1) planes[np++] = d_in[i];
    }
    if (np < 2) return;

    int blocks = CHUNKS_TOTAL / CHUNKS_PER_BLOCK;   // 1024 blocks
    crz_kernel<<<blocks, THREADS>>>(
        (const char*)planes[0],
        (const char*)planes[1],
        angle,
        (char*)d_out);
}

// round 16
// speedup vs baseline: 1.2687x; 1.2687x over previous
#include <cuda_runtime.h>

// CRZ (DIM=2, WIRES=12, control=0, target=1, J=1): diagonal unitary, phase
// depends only on the top two bits of row n (n in [0,4096)), BATCH=2048.
//   region 0,1 (n < 2048)        : d = 1        -> out = x_real (copy!)
//   region 2   (2048 <= n < 3072): d = exp(-i*a), a = 0.5*angle
//   region 3   (3072 <= n < 4096): d = exp(+i*a)
// Harness output is FLOAT32 [D*BATCH] = real part: out = re*pc - im*ps.
//
// R13 resubmit (R14 was an infra failure; kernel never ran).
// Measured-best R8 shape (128-bit, PER_T=4, block-strided, __stcs) plus:
// regions 0/1 (half of all data) have phase==1, so x_imag is never read
// there and out is a bit-exact copy of x_real. Traffic 97.5MB -> 81.5MB.
// Region is uniform per block -> zero divergence.

#define D_DIM   4096
#define BATCH   2048
#define TOTAL   (D_DIM * BATCH)    // 8388608 float32 elements
#define VEC     (TOTAL / 4)        // 2097152 float4 units
#define THREADS 256
#define PER_T   4                  // float4s per thread
#define F4_PER_BLOCK (THREADS * PER_T)   // 1024 float4 = 4096 elems = 2 rows

__global__ __launch_bounds__(THREADS) void crz_kernel(
    const float4* __restrict__ xre,
    const float4* __restrict__ xim,
    const float*  __restrict__ angle,
    float4*       __restrict__ out)
{
    int base = blockIdx.x * F4_PER_BLOCK + threadIdx.x;

    // Block covers elements [blockIdx*4096, +4096); region = elem >> 21
    // -> region = blockIdx >> 9 (uniform across the block; 2048 blocks).
    int region = blockIdx.x >> 9;      // 0..3

    if (region < 2) {
        // Phase == 1: pure copy of x_real; x_imag untouched.
        float4 r0 = xre[base + 0 * THREADS];
        float4 r1 = xre[base + 1 * THREADS];
        float4 r2 = xre[base + 2 * THREADS];
        float4 r3 = xre[base + 3 * THREADS];
        __stcs(&out[base + 0 * THREADS], r0);
        __stcs(&out[base + 1 * THREADS], r1);
        __stcs(&out[base + 2 * THREADS], r2);
        __stcs(&out[base + 3 * THREADS], r3);
        return;
    }

    float a = (angle != nullptr) ? 0.5f * angle[0] : 0.0f;
    float s, c;
    __sincosf(a, &s, &c);

    float pc = c;
    float ps = (region == 2) ? -s : s;

    // Front-batched, fully coalesced loads (8 outstanding LDG.128).
    float4 re0 = xre[base + 0 * THREADS];
    float4 re1 = xre[base + 1 * THREADS];
    float4 re2 = xre[base + 2 * THREADS];
    float4 re3 = xre[base + 3 * THREADS];
    float4 im0 = xim[base + 0 * THREADS];
    float4 im1 = xim[base + 1 * THREADS];
    float4 im2 = xim[base + 2 * THREADS];
    float4 im3 = xim[base + 3 * THREADS];

    float4 o0, o1, o2, o3;
    o0.x = fmaf(re0.x, pc, -im0.x * ps);
    o0.y = fmaf(re0.y, pc, -im0.y * ps);
    o0.z = fmaf(re0.z, pc, -im0.z * ps);
    o0.w = fmaf(re0.w, pc, -im0.w * ps);
    o1.x = fmaf(re1.x, pc, -im1.x * ps);
    o1.y = fmaf(re1.y, pc, -im1.y * ps);
    o1.z = fmaf(re1.z, pc, -im1.z * ps);
    o1.w = fmaf(re1.w, pc, -im1.w * ps);
    o2.x = fmaf(re2.x, pc, -im2.x * ps);
    o2.y = fmaf(re2.y, pc, -im2.y * ps);
    o2.z = fmaf(re2.z, pc, -im2.z * ps);
    o2.w = fmaf(re2.w, pc, -im2.w * ps);
    o3.x = fmaf(re3.x, pc, -im3.x * ps);
    o3.y = fmaf(re3.y, pc, -im3.y * ps);
    o3.z = fmaf(re3.z, pc, -im3.z * ps);
    o3.w = fmaf(re3.w, pc, -im3.w * ps);

    __stcs(&out[base + 0 * THREADS], o0);
    __stcs(&out[base + 1 * THREADS], o1);
    __stcs(&out[base + 2 * THREADS], o2);
    __stcs(&out[base + 3 * THREADS], o3);
}

extern "C" void kernel_launch(void* const* d_in, const int* in_sizes, int n_in,
                              void* d_out, int out_size)
{
    // Size-based mapping: size-1 tensor is angle; the two TOTAL-sized tensors
    // are (x_real, x_imag) in original relative order. Positional fallback.
    const float* angle = nullptr;
    const void* planes[2] = {nullptr, nullptr};
    int np = 0;
    for (int i = 0; i < n_in; i++) {
        if (in_sizes[i] == 1) {
            if (angle == nullptr) angle = (const float*)d_in[i];
        } else if (in_sizes[i] == TOTAL && np < 2) {
            planes[np++] = d_in[i];
        }
    }
    if (np < 2) {
        np = 0;
        for (int i = 0; i < n_in && np < 2; i++)
            if (in_sizes[i] > 1) planes[np++] = d_in[i];
    }
    if (np < 2) return;

    int blocks = VEC / F4_PER_BLOCK;    // 2048 blocks
    crz_kernel<<<blocks, THREADS>>>(
        (const float4*)planes[0],
        (const float4*)planes[1],
        angle,
        (float4*)d_out);
}